// round 16
// baseline (speedup 1.0000x reference)
#include <cuda_runtime.h>
#include <cuda_bf16.h>
#include <cstdint>
#include <cstddef>

#define B_    64
#define L_    256
#define E_    300
#define H_    200
#define NH_   4
#define ENC_  400
#define DH_   100
#define GATE_ 800
#define XCOLS 1600
#define ROWS_ 16384
#define HROW  12      // padded h row stride (floats), conflict-free + 16B aligned

typedef unsigned long long ull;

__device__ __forceinline__ ull pk2(float x, float y) {
    ull r; asm("mov.b64 %0,{%1,%2};" : "=l"(r) : "f"(x), "f"(y)); return r;
}
__device__ __forceinline__ void upk2(ull v, float& x, float& y) {
    asm("mov.b64 {%0,%1},%2;" : "=f"(x), "=f"(y) : "l"(v));
}
__device__ __forceinline__ ull ffma2(ull a, ull b, ull c) {
    ull d; asm("fma.rn.f32x2 %0,%1,%2,%3;" : "=l"(d) : "l"(a), "l"(b), "l"(c)); return d;
}
__device__ __forceinline__ ull fadd2(ull a, ull b) {
    ull d; asm("add.rn.f32x2 %0,%1,%2;" : "=l"(d) : "l"(a), "l"(b)); return d;
}
__device__ __forceinline__ uint32_t smem_u32(const void* p) {
    return (uint32_t)__cvta_generic_to_shared(p);
}
__device__ __forceinline__ void cpa16(uint32_t d, const void* s, bool v) {
    asm volatile("cp.async.cg.shared.global [%0], [%1], 16, %2;"
                 :: "r"(d), "l"(s), "r"(v ? 16 : 0));
}
__device__ __forceinline__ void cpa_commit() { asm volatile("cp.async.commit_group;"); }
template<int N> __device__ __forceinline__ void cpa_wait() {
    asm volatile("cp.async.wait_group %0;" :: "n"(N));
}
__device__ __forceinline__ uint32_t mapa_u32(uint32_t laddr, uint32_t rank) {
    uint32_t r;
    asm volatile("mapa.shared::cluster.u32 %0, %1, %2;" : "=r"(r) : "r"(laddr), "r"(rank));
    return r;
}
__device__ __forceinline__ void st_cluster_f32(uint32_t addr, float v) {
    asm volatile("st.shared::cluster.f32 [%0], %1;" :: "r"(addr), "f"(v) : "memory");
}

__device__ float g_xproj[(size_t)ROWS_ * XCOLS];
__device__ float g_h1[(size_t)ROWS_ * ENC_];
__device__ float g_KV[(size_t)ROWS_ * 800];
__device__ float g_p[B_ * NH_ * L_];
__device__ float g_pooled[B_ * ENC_];
__device__ float g_weff[ENC_];
__device__ int g_len[B_];
__device__ int g_mstride;

// ---- init ----
__global__ __launch_bounds__(512) void init_kernel(const unsigned char* __restrict__ mask,
                                                   const float* __restrict__ Wo,
                                                   const float* __restrict__ outW) {
    int tid = threadIdx.x;
    int ms = (mask[1] == 0) ? 4 : 1;  // bool vs int32 mask
    if (tid == 0) g_mstride = ms;
    if (tid < B_) {
        int s = 0;
        for (int t = 0; t < L_; t++) s += (mask[(size_t)(tid * L_ + t) * ms] != 0) ? 1 : 0;
        g_len[tid] = s;
    }
    int warp = tid >> 5, lane = tid & 31;
    for (int i = warp; i < ENC_; i += 16) {
        float s = 0.f;
        for (int j = lane; j < ENC_; j += 32) s += Wo[i * ENC_ + j] * outW[j];
#pragma unroll
        for (int o = 16; o; o >>= 1) s += __shfl_xor_sync(0xffffffffu, s, o);
        if (lane == 0) g_weff[i] = s;
    }
}

__device__ __forceinline__ bool mk(const unsigned char* m, int idx) {
    return m[(size_t)idx * g_mstride] != 0;
}
__device__ __forceinline__ float sigm(float x) { return 1.f / (1.f + expf(-x)); }

__device__ __forceinline__ float4 ld4g(const float* p, int k, int lim) {
    if (k + 3 < lim) return *(const float4*)(p + k);
    float4 v;
    v.x = (k + 0 < lim) ? p[k + 0] : 0.f;
    v.y = (k + 1 < lim) ? p[k + 1] : 0.f;
    v.z = (k + 2 < lim) ? p[k + 2] : 0.f;
    v.w = (k + 3 < lim) ? p[k + 3] : 0.f;
    return v;
}

// ---- GEMM1: xproj = embed_W[x] @ [Wi_f|Wi_b] + bias, KTILE=16 pipelined ----
__global__ __launch_bounds__(256) void gemm_xproj_kernel(
    const int* __restrict__ x, const float* __restrict__ embW,
    const float* __restrict__ Wif, const float* __restrict__ Wib,
    const float* __restrict__ bf, const float* __restrict__ bb) {
    __shared__ float As[2][16][132];
    __shared__ float Bs[2][16][132];
    __shared__ int tok[128];
    const int NT = 19;
    int bn = blockIdx.x * 128, bm = blockIdx.y * 128;
    int tid = threadIdx.x, tx = tid & 15, ty = tid >> 4;
    if (tid < 128) tok[tid] = x[bm + tid];
    __syncthreads();
    ull acc2[8][4];
#pragma unroll
    for (int i = 0; i < 8; i++)
#pragma unroll
        for (int j = 0; j < 4; j++) acc2[i][j] = 0ULL;
    int ar = tid >> 1, akb = (tid & 1) * 8;
    int bk = tid >> 5, bcb = (tid & 31) * 4;
    const float* arow = embW + (size_t)tok[ar] * E_;
    int bcol = bn + bcb;
    bool bcok = (bcol + 3) < XCOLS;
    const float* bsrcf = Wif + bcol;
    const float* bsrcb = Wib + (bcol - GATE_);

    float4 a0R, a1R, a0N, a1N;
    {
        a0R = ld4g(arow, akb, E_);
        a1R = ld4g(arow, akb + 4, E_);
        const float* base = (bcol < GATE_) ? bsrcf : bsrcb;
        cpa16(smem_u32(&Bs[0][bk][bcb]),     base + (size_t)bk * GATE_,       bcok && (bk < E_));
        cpa16(smem_u32(&Bs[0][bk + 8][bcb]), base + (size_t)(bk + 8) * GATE_, bcok && (bk + 8 < E_));
        cpa_commit();
    }
    for (int it = 0; it < NT; ++it) {
        int buf = it & 1;
        As[buf][akb + 0][ar] = a0R.x; As[buf][akb + 1][ar] = a0R.y;
        As[buf][akb + 2][ar] = a0R.z; As[buf][akb + 3][ar] = a0R.w;
        As[buf][akb + 4][ar] = a1R.x; As[buf][akb + 5][ar] = a1R.y;
        As[buf][akb + 6][ar] = a1R.z; As[buf][akb + 7][ar] = a1R.w;
        if (it + 1 < NT) {
            int k0 = (it + 1) * 16;
            a0N = ld4g(arow, k0 + akb, E_);
            a1N = ld4g(arow, k0 + akb + 4, E_);
            const float* base = (bcol < GATE_) ? bsrcf : bsrcb;
            int kb0 = k0 + bk, kb1 = k0 + bk + 8;
            cpa16(smem_u32(&Bs[buf ^ 1][bk][bcb]),     base + (size_t)kb0 * GATE_, bcok && (kb0 < E_));
            cpa16(smem_u32(&Bs[buf ^ 1][bk + 8][bcb]), base + (size_t)kb1 * GATE_, bcok && (kb1 < E_));
            cpa_commit();
            cpa_wait<1>();
        } else {
            cpa_wait<0>();
        }
        __syncthreads();
#pragma unroll
        for (int k = 0; k < 16; k++) {
            float4 a0 = *(const float4*)&As[buf][k][ty * 8];
            float4 a1 = *(const float4*)&As[buf][k][ty * 8 + 4];
            float4 b0 = *(const float4*)&Bs[buf][k][tx * 8];
            float4 b1 = *(const float4*)&Bs[buf][k][tx * 8 + 4];
            float a[8] = {a0.x, a0.y, a0.z, a0.w, a1.x, a1.y, a1.z, a1.w};
            ull bb2[4] = {pk2(b0.x, b0.y), pk2(b0.z, b0.w), pk2(b1.x, b1.y), pk2(b1.z, b1.w)};
#pragma unroll
            for (int i = 0; i < 8; i++) {
                ull ad = pk2(a[i], a[i]);
#pragma unroll
                for (int j = 0; j < 4; j++) acc2[i][j] = ffma2(ad, bb2[j], acc2[i][j]);
            }
        }
        __syncthreads();
        a0R = a0N; a1R = a1N;
    }
#pragma unroll
    for (int i = 0; i < 8; i++) {
        int r = bm + ty * 8 + i;
#pragma unroll
        for (int j = 0; j < 4; j++) {
            float v0, v1; upk2(acc2[i][j], v0, v1);
            int c = bn + tx * 8 + 2 * j;
            if (c < XCOLS) {
                float bias = (c < GATE_) ? bf[c] : bb[c - GATE_];
                g_xproj[(size_t)r * XCOLS + c] = v0 + bias;
            }
            if (c + 1 < XCOLS) {
                float bias = (c + 1 < GATE_) ? bf[c + 1] : bb[c + 1 - GATE_];
                g_xproj[(size_t)r * XCOLS + c + 1] = v1 + bias;
            }
        }
    }
}

// ---- biLSTM: cluster-local batch groups, DSMEM h exchange, NO global barrier ----
// 128 CTAs = 2 dirs x 8 clusters x 8 CTAs. Cluster owns 8 batches; CTA rank owns
// 25 units. Thread t<200: u = t>>3 (unit), ks = t&7 (k-octant AND epilogue batch).
__global__ __launch_bounds__(224, 1) __cluster_dims__(8, 1, 1)
void lstm_kernel(const float* __restrict__ Whf, const float* __restrict__ Whb) {
    __shared__ __align__(16) float h_s[2][H_ * HROW];  // 19.2 KB, double buffered
    int blk = blockIdx.x;
    int dir = blk >> 6;
    int cl = (blk >> 3) & 7;
    uint32_t rank;
    asm("mov.u32 %0, %%cluster_ctarank;" : "=r"(rank));
    const float* Wh = dir ? Whb : Whf;
    int t = threadIdx.x;
    int u = t >> 3, ks = t & 7;
    bool active = (t < 200);
    int ucol = rank * 25 + u; if (ucol > 199) ucol = 199;
    int bglob = cl * 8 + ks;
    int mylen = g_len[bglob];

    // Wh slice in registers: w[kk][g] for k = ks*25+kk, column ucol
    float w[25][4];
#pragma unroll
    for (int kk = 0; kk < 25; kk++)
#pragma unroll
        for (int g = 0; g < 4; g++)
            w[kk][g] = Wh[(ks * 25 + kk) * GATE_ + g * H_ + ucol];

    // remote smem bases (fixed layout -> hoist mapa)
    uint32_t lbase = smem_u32(&h_s[0][0]);
    uint32_t rbase[8];
#pragma unroll
    for (int r = 0; r < 8; r++) rbase[r] = mapa_u32(lbase, (uint32_t)r);

    // zero read buffer 0
    for (int i = t; i < H_ * HROW; i += 224) h_s[0][i] = 0.f;
    __syncthreads();

    float c = 0.f;
    float xg[4];
    {
        int t0 = dir ? (L_ - 1) : 0;
        const float* xp = g_xproj + (size_t)(bglob * L_ + t0) * XCOLS + dir * GATE_ + ucol;
#pragma unroll
        for (int g = 0; g < 4; g++) xg[g] = active ? __ldg(&xp[g * H_]) : 0.f;
    }
    // align cluster before first DSMEM writes
    asm volatile("barrier.cluster.arrive.aligned;" ::: "memory");
    asm volatile("barrier.cluster.wait.aligned;" ::: "memory");

    int rbuf = 0;
    for (int step = 0; step < L_; step++) {
        int tt = dir ? (L_ - 1 - step) : step;
        int wbuf = rbuf ^ 1;

        // acc2[bp][g]: halves = batches (cl*8 + 2bp, +1)
        ull acc[4][4];
#pragma unroll
        for (int bp = 0; bp < 4; bp++)
#pragma unroll
            for (int g = 0; g < 4; g++) acc[bp][g] = 0ULL;

        const float* hb = &h_s[rbuf][0];
#pragma unroll
        for (int kk = 0; kk < 25; kk++) {
            int k = ks * 25 + kk;
            const ull* hp8 = (const ull*)(hb + k * HROW);
            ull hp[4] = {hp8[0], hp8[1], hp8[2], hp8[3]};
#pragma unroll
            for (int g = 0; g < 4; g++) {
                ull wd = pk2(w[kk][g], w[kk][g]);
#pragma unroll
                for (int bp = 0; bp < 4; bp++) acc[bp][g] = ffma2(hp[bp], wd, acc[bp][g]);
            }
        }
        // butterfly over ks bits (partners share the same u)
#pragma unroll
        for (int bp = 0; bp < 4; bp++)
#pragma unroll
            for (int g = 0; g < 4; g++) {
                ull v = acc[bp][g];
                v = fadd2(v, __shfl_xor_sync(0xffffffffu, v, 1));
                v = fadd2(v, __shfl_xor_sync(0xffffffffu, v, 2));
                v = fadd2(v, __shfl_xor_sync(0xffffffffu, v, 4));
                acc[bp][g] = v;
            }
        // epilogue: lane handles (unit ucol, batch bglob)
        float hout = 0.f;
        {
            int mybp = ks >> 1;
            bool odd = ks & 1;
            float gv[4];
#pragma unroll
            for (int g = 0; g < 4; g++) {
                float lo, hi; upk2(acc[mybp][g], lo, hi);
                gv[g] = (odd ? hi : lo) + xg[g];
            }
            float cn = sigm(gv[1]) * c + sigm(gv[0]) * tanhf(gv[2]);
            float hn = sigm(gv[3]) * tanhf(cn);
            bool m = (tt < mylen);
            hout = m ? hn : h_s[rbuf][ucol * HROW + ks];
            if (m) c = cn;
        }
        if (active) {
            // broadcast new h to all 8 CTAs (incl. self)
            uint32_t off = (uint32_t)((wbuf * (H_ * HROW) + ucol * HROW + ks) * 4);
#pragma unroll
            for (int r = 0; r < 8; r++) st_cluster_f32(rbase[r] + off, hout);
            g_h1[(size_t)(bglob * L_ + tt) * ENC_ + dir * H_ + ucol] = hout;
            if (step + 1 < L_) {
                int tn = dir ? (L_ - 2 - step) : (step + 1);
                const float* xp = g_xproj + (size_t)(bglob * L_ + tn) * XCOLS + dir * GATE_ + ucol;
#pragma unroll
                for (int g = 0; g < 4; g++) xg[g] = __ldg(&xp[g * H_]);
            }
        }
        // cluster barrier: release our stores, acquire peers'
        asm volatile("barrier.cluster.arrive.aligned;" ::: "memory");
        asm volatile("barrier.cluster.wait.aligned;" ::: "memory");
        rbuf = wbuf;
    }
}

// ---- GEMM2: KV = h1 @ [Wk|Wv], KTILE=16 pipelined ----
__global__ __launch_bounds__(256) void gemm_kv_kernel(
    const float* __restrict__ Wk, const float* __restrict__ Wv) {
    __shared__ float As[2][16][132];
    __shared__ float Bs[2][16][132];
    const int NT = 25;
    int bn = blockIdx.x * 128, bm = blockIdx.y * 128;
    int tid = threadIdx.x, tx = tid & 15, ty = tid >> 4;
    ull acc2[8][4];
#pragma unroll
    for (int i = 0; i < 8; i++)
#pragma unroll
        for (int j = 0; j < 4; j++) acc2[i][j] = 0ULL;
    int ar = tid >> 1, akb = (tid & 1) * 8;
    int bk = tid >> 5, bcb = (tid & 31) * 4;
    const float* arow = g_h1 + (size_t)(bm + ar) * ENC_;
    int bcol = bn + bcb;
    bool bcok = (bcol + 3) < 800;
    const float* bsrc = (bcol < ENC_) ? (Wk + bcol) : (Wv + (bcol - ENC_));

    float4 a0R, a1R, a0N, a1N;
    {
        a0R = *(const float4*)(arow + akb);
        a1R = *(const float4*)(arow + akb + 4);
        cpa16(smem_u32(&Bs[0][bk][bcb]),     bsrc + (size_t)bk * ENC_,       bcok);
        cpa16(smem_u32(&Bs[0][bk + 8][bcb]), bsrc + (size_t)(bk + 8) * ENC_, bcok);
        cpa_commit();
    }
    for (int it = 0; it < NT; ++it) {
        int buf = it & 1;
        As[buf][akb + 0][ar] = a0R.x; As[buf][akb + 1][ar] = a0R.y;
        As[buf][akb + 2][ar] = a0R.z; As[buf][akb + 3][ar] = a0R.w;
        As[buf][akb + 4][ar] = a1R.x; As[buf][akb + 5][ar] = a1R.y;
        As[buf][akb + 6][ar] = a1R.z; As[buf][akb + 7][ar] = a1R.w;
        if (it + 1 < NT) {
            int k0 = (it + 1) * 16;
            a0N = *(const float4*)(arow + k0 + akb);
            a1N = *(const float4*)(arow + k0 + akb + 4);
            cpa16(smem_u32(&Bs[buf ^ 1][bk][bcb]),     bsrc + (size_t)(k0 + bk) * ENC_,     bcok);
            cpa16(smem_u32(&Bs[buf ^ 1][bk + 8][bcb]), bsrc + (size_t)(k0 + bk + 8) * ENC_, bcok);
            cpa_commit();
            cpa_wait<1>();
        } else {
            cpa_wait<0>();
        }
        __syncthreads();
#pragma unroll
        for (int k = 0; k < 16; k++) {
            float4 a0 = *(const float4*)&As[buf][k][ty * 8];
            float4 a1 = *(const float4*)&As[buf][k][ty * 8 + 4];
            float4 b0 = *(const float4*)&Bs[buf][k][tx * 8];
            float4 b1 = *(const float4*)&Bs[buf][k][tx * 8 + 4];
            float a[8] = {a0.x, a0.y, a0.z, a0.w, a1.x, a1.y, a1.z, a1.w};
            ull bb2[4] = {pk2(b0.x, b0.y), pk2(b0.z, b0.w), pk2(b1.x, b1.y), pk2(b1.z, b1.w)};
#pragma unroll
            for (int i = 0; i < 8; i++) {
                ull ad = pk2(a[i], a[i]);
#pragma unroll
                for (int j = 0; j < 4; j++) acc2[i][j] = ffma2(ad, bb2[j], acc2[i][j]);
            }
        }
        __syncthreads();
        a0R = a0N; a1R = a1N;
    }
#pragma unroll
    for (int i = 0; i < 8; i++) {
        int r = bm + ty * 8 + i;
#pragma unroll
        for (int j = 0; j < 4; j++) {
            float v0, v1; upk2(acc2[i][j], v0, v1);
            int cix = bn + tx * 8 + 2 * j;
            if (cix < 800) g_KV[(size_t)r * 800 + cix] = v0;
            if (cix + 1 < 800) g_KV[(size_t)r * 800 + cix + 1] = v1;
        }
    }
}

__device__ __forceinline__ float bsum(float v, float* red) {
#pragma unroll
    for (int o = 16; o; o >>= 1) v += __shfl_xor_sync(0xffffffffu, v, o);
    int lane = threadIdx.x & 31, warp = threadIdx.x >> 5;
    __syncthreads();
    if (lane == 0) red[warp] = v;
    __syncthreads();
    float r = red[0];
#pragma unroll
    for (int i = 1; i < 8; i++) r += red[i];
    return r;
}
__device__ __forceinline__ float bmax(float v, float* red) {
#pragma unroll
    for (int o = 16; o; o >>= 1) v = fmaxf(v, __shfl_xor_sync(0xffffffffu, v, o));
    int lane = threadIdx.x & 31, warp = threadIdx.x >> 5;
    __syncthreads();
    if (lane == 0) red[warp] = v;
    __syncthreads();
    float r = red[0];
#pragma unroll
    for (int i = 1; i < 8; i++) r = fmaxf(r, red[i]);
    return r;
}

// ---- budget projection with fused score computation, block per (b,h) ----
__global__ __launch_bounds__(256) void budget_kernel(const float* __restrict__ q,
                                                     const unsigned char* __restrict__ mask) {
    __shared__ float red[8];
    __shared__ float qs[DH_];
    int b = blockIdx.x, h = blockIdx.y, l = threadIdx.x;
    if (l < DH_) qs[l] = q[h * DH_ + l];
    __syncthreads();

    const float4* kr = (const float4*)(g_KV + (size_t)(b * L_ + l) * 800 + h * DH_);
    const float4* q4 = (const float4*)qs;
    float a0 = 0.f, a1 = 0.f;
#pragma unroll
    for (int i = 0; i < 25; i += 2) {
        float4 v = kr[i], qv = q4[i];
        a0 += v.x * qv.x + v.y * qv.y + v.z * qv.z + v.w * qv.w;
        if (i + 1 < 25) {
            float4 v2 = kr[i + 1], qv2 = q4[i + 1];
            a1 += v2.x * qv2.x + v2.y * qv2.y + v2.z * qv2.z + v2.w * qv2.w;
        }
    }
    float s_raw = 1000.0f * (a0 + a1);

    bool m = mk(mask, b * L_ + l);
    float s = m ? s_raw : -1e9f;
    float budget = roundf(0.2f * (float)g_len[b]);
    float p0 = fminf(fmaxf(s, 0.f), 1.f);
    bool need = bsum(p0, red) > budget;
    float hi = bmax(m ? s : 0.f, red) + 1.f;
    float lo = 0.f;
    for (int it = 0; it < 60; it++) {
        float mid = 0.5f * (lo + hi);
        float val = bsum(fminf(fmaxf(s - mid, 0.f), 1.f), red);
        if (val > budget) lo = mid; else hi = mid;
    }
    float tau0 = 0.5f * (lo + hi);
    float r = s - tau0;
    bool fr = (r > 0.f) && (r < 1.f) && m;
    bool h1f = (r >= 1.f) && m;
    float nfree = bsum(fr ? 1.f : 0.f, red);
    float sfree = bsum(fr ? s : 0.f, red);
    float nhi = bsum(h1f ? 1.f : 0.f, red);
    float tau = (sfree + nhi - budget) / fmaxf(nfree, 1.f);
    tau = (nfree > 0.f) ? tau : tau0;
    float pv = fminf(fmaxf(s - tau, 0.f), 1.f);
    g_p[((b * NH_ + h) << 8) + l] = need ? pv : p0;
}

// ---- zp ----
__global__ void zp_kernel(const unsigned char* __restrict__ mask, float* __restrict__ out) {
    int b = blockIdx.x, l = threadIdx.x;
    float v = 0.f;
    if (mk(mask, b * L_ + l))
        v = 0.25f * (g_p[((b * NH_) << 8) + l] + g_p[((b * NH_ + 1) << 8) + l] +
                     g_p[((b * NH_ + 2) << 8) + l] + g_p[((b * NH_ + 3) << 8) + l]);
    out[B_ + b * L_ + l] = v;
}

// ---- pooled ----
__global__ __launch_bounds__(128) void pooled_kernel() {
    __shared__ float ps[L_];
    int b = blockIdx.x, h = blockIdx.y, d = threadIdx.x;
    for (int i = d; i < L_; i += 128) ps[i] = g_p[((b * NH_ + h) << 8) + i];
    __syncthreads();
    if (d >= DH_) return;
    const float* vb = g_KV + (size_t)(b * L_) * 800 + ENC_ + h * DH_ + d;
    float a0 = 0.f, a1 = 0.f, a2 = 0.f, a3 = 0.f;
#pragma unroll 4
    for (int l = 0; l < L_; l += 4) {
        a0 += ps[l] * vb[(size_t)l * 800];
        a1 += ps[l + 1] * vb[(size_t)(l + 1) * 800];
        a2 += ps[l + 2] * vb[(size_t)(l + 2) * 800];
        a3 += ps[l + 3] * vb[(size_t)(l + 3) * 800];
    }
    g_pooled[b * ENC_ + h * DH_ + d] = (a0 + a1) + (a2 + a3);
}

// ---- y ----
__global__ __launch_bounds__(128) void final_kernel(const float* __restrict__ outb,
                                                    float* __restrict__ out) {
    __shared__ float red[4];
    int b = blockIdx.x, tid = threadIdx.x;
    float v = 0.f;
    for (int i = tid; i < ENC_; i += 128) v += g_pooled[b * ENC_ + i] * g_weff[i];
#pragma unroll
    for (int o = 16; o; o >>= 1) v += __shfl_xor_sync(0xffffffffu, v, o);
    if ((tid & 31) == 0) red[tid >> 5] = v;
    __syncthreads();
    if (tid == 0) out[b] = sigm(red[0] + red[1] + red[2] + red[3] + outb[0]);
}

extern "C" void kernel_launch(void* const* d_in, const int* in_sizes, int n_in,
                              void* d_out, int out_size) {
    const int* x = (const int*)d_in[0];
    const unsigned char* mask = (const unsigned char*)d_in[2];
    const float* embW = (const float*)d_in[3];
    const float* Wif = (const float*)d_in[4];
    const float* Whf = (const float*)d_in[5];
    const float* bf = (const float*)d_in[6];
    const float* Wib = (const float*)d_in[7];
    const float* Whb = (const float*)d_in[8];
    const float* bb = (const float*)d_in[9];
    const float* Wk = (const float*)d_in[10];
    const float* Wv = (const float*)d_in[11];
    const float* q = (const float*)d_in[12];
    const float* Wo = (const float*)d_in[13];
    const float* outW = (const float*)d_in[14];
    const float* outb = (const float*)d_in[15];
    float* out = (float*)d_out;

    init_kernel<<<1, 512>>>(mask, Wo, outW);
    gemm_xproj_kernel<<<dim3(13, 128), 256>>>(x, embW, Wif, Wib, bf, bb);
    lstm_kernel<<<128, 224>>>(Whf, Whb);
    gemm_kv_kernel<<<dim3(7, 128), 256>>>(Wk, Wv);
    budget_kernel<<<dim3(B_, NH_), 256>>>(q, mask);
    zp_kernel<<<B_, L_>>>(mask, out);
    pooled_kernel<<<dim3(B_, NH_), 128>>>();
    final_kernel<<<B_, 128>>>(outb, out);
}

// round 17
// speedup vs baseline: 1.1336x; 1.1336x over previous
#include <cuda_runtime.h>
#include <cuda_bf16.h>
#include <cstdint>
#include <cstddef>

#define B_    64
#define L_    256
#define E_    300
#define H_    200
#define NH_   4
#define ENC_  400
#define DH_   100
#define GATE_ 800
#define XCOLS 1600
#define ROWS_ 16384
#define HROW  12      // padded h row stride (floats)

typedef unsigned long long ull;

__device__ __forceinline__ ull pk2(float x, float y) {
    ull r; asm("mov.b64 %0,{%1,%2};" : "=l"(r) : "f"(x), "f"(y)); return r;
}
__device__ __forceinline__ void upk2(ull v, float& x, float& y) {
    asm("mov.b64 {%0,%1},%2;" : "=f"(x), "=f"(y) : "l"(v));
}
__device__ __forceinline__ ull ffma2(ull a, ull b, ull c) {
    ull d; asm("fma.rn.f32x2 %0,%1,%2,%3;" : "=l"(d) : "l"(a), "l"(b), "l"(c)); return d;
}
__device__ __forceinline__ ull fadd2(ull a, ull b) {
    ull d; asm("add.rn.f32x2 %0,%1,%2;" : "=l"(d) : "l"(a), "l"(b)); return d;
}
__device__ __forceinline__ uint32_t smem_u32(const void* p) {
    return (uint32_t)__cvta_generic_to_shared(p);
}
__device__ __forceinline__ void cpa16(uint32_t d, const void* s, bool v) {
    asm volatile("cp.async.cg.shared.global [%0], [%1], 16, %2;"
                 :: "r"(d), "l"(s), "r"(v ? 16 : 0));
}
__device__ __forceinline__ void cpa_commit() { asm volatile("cp.async.commit_group;"); }
template<int N> __device__ __forceinline__ void cpa_wait() {
    asm volatile("cp.async.wait_group %0;" :: "n"(N));
}
__device__ __forceinline__ uint32_t mapa_u32(uint32_t laddr, uint32_t rank) {
    uint32_t r;
    asm volatile("mapa.shared::cluster.u32 %0, %1, %2;" : "=r"(r) : "r"(laddr), "r"(rank));
    return r;
}
__device__ __forceinline__ void st_cluster_f32(uint32_t addr, float v) {
    asm volatile("st.shared::cluster.f32 [%0], %1;" :: "r"(addr), "f"(v) : "memory");
}

__device__ float g_xproj[(size_t)ROWS_ * XCOLS];
__device__ float g_h1[(size_t)ROWS_ * ENC_];
__device__ float g_KV[(size_t)ROWS_ * 800];
__device__ float g_p[B_ * NH_ * L_];
__device__ float g_pooled[B_ * ENC_];
__device__ float g_weff[ENC_];
__device__ int g_len[B_];
__device__ int g_mstride;

// ---- init ----
__global__ __launch_bounds__(512) void init_kernel(const unsigned char* __restrict__ mask,
                                                   const float* __restrict__ Wo,
                                                   const float* __restrict__ outW) {
    int tid = threadIdx.x;
    int ms = (mask[1] == 0) ? 4 : 1;  // bool vs int32 mask
    if (tid == 0) g_mstride = ms;
    if (tid < B_) {
        int s = 0;
        for (int t = 0; t < L_; t++) s += (mask[(size_t)(tid * L_ + t) * ms] != 0) ? 1 : 0;
        g_len[tid] = s;
    }
    int warp = tid >> 5, lane = tid & 31;
    for (int i = warp; i < ENC_; i += 16) {
        float s = 0.f;
        for (int j = lane; j < ENC_; j += 32) s += Wo[i * ENC_ + j] * outW[j];
#pragma unroll
        for (int o = 16; o; o >>= 1) s += __shfl_xor_sync(0xffffffffu, s, o);
        if (lane == 0) g_weff[i] = s;
    }
}

__device__ __forceinline__ bool mk(const unsigned char* m, int idx) {
    return m[(size_t)idx * g_mstride] != 0;
}
__device__ __forceinline__ float sigm(float x) { return 1.f / (1.f + expf(-x)); }

__device__ __forceinline__ float4 ld4g(const float* p, int k, int lim) {
    if (k + 3 < lim) return *(const float4*)(p + k);
    float4 v;
    v.x = (k + 0 < lim) ? p[k + 0] : 0.f;
    v.y = (k + 1 < lim) ? p[k + 1] : 0.f;
    v.z = (k + 2 < lim) ? p[k + 2] : 0.f;
    v.w = (k + 3 < lim) ? p[k + 3] : 0.f;
    return v;
}

// ---- GEMM1: xproj = embed_W[x] @ [Wi_f|Wi_b] + bias, KTILE=16 pipelined ----
__global__ __launch_bounds__(256) void gemm_xproj_kernel(
    const int* __restrict__ x, const float* __restrict__ embW,
    const float* __restrict__ Wif, const float* __restrict__ Wib,
    const float* __restrict__ bf, const float* __restrict__ bb) {
    __shared__ float As[2][16][132];
    __shared__ float Bs[2][16][132];
    __shared__ int tok[128];
    const int NT = 19;
    int bn = blockIdx.x * 128, bm = blockIdx.y * 128;
    int tid = threadIdx.x, tx = tid & 15, ty = tid >> 4;
    if (tid < 128) tok[tid] = x[bm + tid];
    __syncthreads();
    ull acc2[8][4];
#pragma unroll
    for (int i = 0; i < 8; i++)
#pragma unroll
        for (int j = 0; j < 4; j++) acc2[i][j] = 0ULL;
    int ar = tid >> 1, akb = (tid & 1) * 8;
    int bk = tid >> 5, bcb = (tid & 31) * 4;
    const float* arow = embW + (size_t)tok[ar] * E_;
    int bcol = bn + bcb;
    bool bcok = (bcol + 3) < XCOLS;
    const float* bsrcf = Wif + bcol;
    const float* bsrcb = Wib + (bcol - GATE_);

    float4 a0R, a1R, a0N, a1N;
    {
        a0R = ld4g(arow, akb, E_);
        a1R = ld4g(arow, akb + 4, E_);
        const float* base = (bcol < GATE_) ? bsrcf : bsrcb;
        cpa16(smem_u32(&Bs[0][bk][bcb]),     base + (size_t)bk * GATE_,       bcok && (bk < E_));
        cpa16(smem_u32(&Bs[0][bk + 8][bcb]), base + (size_t)(bk + 8) * GATE_, bcok && (bk + 8 < E_));
        cpa_commit();
    }
    for (int it = 0; it < NT; ++it) {
        int buf = it & 1;
        As[buf][akb + 0][ar] = a0R.x; As[buf][akb + 1][ar] = a0R.y;
        As[buf][akb + 2][ar] = a0R.z; As[buf][akb + 3][ar] = a0R.w;
        As[buf][akb + 4][ar] = a1R.x; As[buf][akb + 5][ar] = a1R.y;
        As[buf][akb + 6][ar] = a1R.z; As[buf][akb + 7][ar] = a1R.w;
        if (it + 1 < NT) {
            int k0 = (it + 1) * 16;
            a0N = ld4g(arow, k0 + akb, E_);
            a1N = ld4g(arow, k0 + akb + 4, E_);
            const float* base = (bcol < GATE_) ? bsrcf : bsrcb;
            int kb0 = k0 + bk, kb1 = k0 + bk + 8;
            cpa16(smem_u32(&Bs[buf ^ 1][bk][bcb]),     base + (size_t)kb0 * GATE_, bcok && (kb0 < E_));
            cpa16(smem_u32(&Bs[buf ^ 1][bk + 8][bcb]), base + (size_t)kb1 * GATE_, bcok && (kb1 < E_));
            cpa_commit();
            cpa_wait<1>();
        } else {
            cpa_wait<0>();
        }
        __syncthreads();
#pragma unroll
        for (int k = 0; k < 16; k++) {
            float4 a0 = *(const float4*)&As[buf][k][ty * 8];
            float4 a1 = *(const float4*)&As[buf][k][ty * 8 + 4];
            float4 b0 = *(const float4*)&Bs[buf][k][tx * 8];
            float4 b1 = *(const float4*)&Bs[buf][k][tx * 8 + 4];
            float a[8] = {a0.x, a0.y, a0.z, a0.w, a1.x, a1.y, a1.z, a1.w};
            ull bb2[4] = {pk2(b0.x, b0.y), pk2(b0.z, b0.w), pk2(b1.x, b1.y), pk2(b1.z, b1.w)};
#pragma unroll
            for (int i = 0; i < 8; i++) {
                ull ad = pk2(a[i], a[i]);
#pragma unroll
                for (int j = 0; j < 4; j++) acc2[i][j] = ffma2(ad, bb2[j], acc2[i][j]);
            }
        }
        __syncthreads();
        a0R = a0N; a1R = a1N;
    }
#pragma unroll
    for (int i = 0; i < 8; i++) {
        int r = bm + ty * 8 + i;
#pragma unroll
        for (int j = 0; j < 4; j++) {
            float v0, v1; upk2(acc2[i][j], v0, v1);
            int c = bn + tx * 8 + 2 * j;
            if (c < XCOLS) {
                float bias = (c < GATE_) ? bf[c] : bb[c - GATE_];
                g_xproj[(size_t)r * XCOLS + c] = v0 + bias;
            }
            if (c + 1 < XCOLS) {
                float bias = (c + 1 < GATE_) ? bf[c + 1] : bb[c + 1 - GATE_];
                g_xproj[(size_t)r * XCOLS + c + 1] = v1 + bias;
            }
        }
    }
}

// ---- biLSTM: 8-CTA clusters, DSMEM h exchange, mbarrier sync (no IVALL) ----
// 128 CTAs = 2 dirs x 8 clusters x 8 CTAs. Cluster owns 8 batches; CTA rank owns
// 25 units. Thread t<200: u = t>>3, ks = t&7 (k-octant AND epilogue batch).
// Each phase expects 56 arrivals (8 CTAs x 7 warps).
__global__ __launch_bounds__(224, 1) __cluster_dims__(8, 1, 1)
void lstm_kernel(const float* __restrict__ Whf, const float* __restrict__ Whb) {
    __shared__ __align__(16) float h_s[2][H_ * HROW];
    __shared__ __align__(8) unsigned long long mbar_s;
    int blk = blockIdx.x;
    int dir = blk >> 6;
    int cl = (blk >> 3) & 7;
    uint32_t rank;
    asm("mov.u32 %0, %%cluster_ctarank;" : "=r"(rank));
    const float* Wh = dir ? Whb : Whf;
    int t = threadIdx.x;
    int lane = t & 31;
    int u = t >> 3, ks = t & 7;
    bool active = (t < 200);
    int ucol = rank * 25 + u; if (ucol > 199) ucol = 199;
    int bglob = cl * 8 + ks;
    int mylen = g_len[bglob];
    uint32_t mbar = smem_u32(&mbar_s);

    if (t == 0)
        asm volatile("mbarrier.init.shared.b64 [%0], 56;" :: "r"(mbar) : "memory");

    float w[25][4];
#pragma unroll
    for (int kk = 0; kk < 25; kk++)
#pragma unroll
        for (int g = 0; g < 4; g++)
            w[kk][g] = Wh[(ks * 25 + kk) * GATE_ + g * H_ + ucol];

    uint32_t lbase = smem_u32(&h_s[0][0]);
    uint32_t rbase[8];
#pragma unroll
    for (int r = 0; r < 8; r++) rbase[r] = mapa_u32(lbase, (uint32_t)r);
    uint32_t mbar_peer = mapa_u32(mbar, (uint32_t)(lane & 7));

    for (int i = t; i < H_ * HROW; i += 224) h_s[0][i] = 0.f;
    __syncthreads();

    float c = 0.f;
    float xg[4];
    {
        int t0 = dir ? (L_ - 1) : 0;
        const float* xp = g_xproj + (size_t)(bglob * L_ + t0) * XCOLS + dir * GATE_ + ucol;
#pragma unroll
        for (int g = 0; g < 4; g++) xg[g] = active ? __ldg(&xp[g * H_]) : 0.f;
    }
    // one-time alignment (mbarrier init visible before any remote arrive)
    asm volatile("barrier.cluster.arrive.aligned;" ::: "memory");
    asm volatile("barrier.cluster.wait.aligned;" ::: "memory");

    int rbuf = 0;
    for (int step = 0; step < L_; step++) {
        int tt = dir ? (L_ - 1 - step) : step;
        int wbuf = rbuf ^ 1;
        bool last = (step == L_ - 1);

        ull acc[4][4];
#pragma unroll
        for (int bp = 0; bp < 4; bp++)
#pragma unroll
            for (int g = 0; g < 4; g++) acc[bp][g] = 0ULL;

        const float* hb = &h_s[rbuf][0];
#pragma unroll
        for (int kk = 0; kk < 25; kk++) {
            int k = ks * 25 + kk;
            const ull* hp8 = (const ull*)(hb + k * HROW);
            ull hp[4] = {hp8[0], hp8[1], hp8[2], hp8[3]};
#pragma unroll
            for (int g = 0; g < 4; g++) {
                ull wd = pk2(w[kk][g], w[kk][g]);
#pragma unroll
                for (int bp = 0; bp < 4; bp++) acc[bp][g] = ffma2(hp[bp], wd, acc[bp][g]);
            }
        }
#pragma unroll
        for (int bp = 0; bp < 4; bp++)
#pragma unroll
            for (int g = 0; g < 4; g++) {
                ull v = acc[bp][g];
                v = fadd2(v, __shfl_xor_sync(0xffffffffu, v, 1));
                v = fadd2(v, __shfl_xor_sync(0xffffffffu, v, 2));
                v = fadd2(v, __shfl_xor_sync(0xffffffffu, v, 4));
                acc[bp][g] = v;
            }
        float hout = 0.f;
        {
            int mybp = ks >> 1;
            bool odd = ks & 1;
            float gv[4];
#pragma unroll
            for (int g = 0; g < 4; g++) {
                float lo, hi; upk2(acc[mybp][g], lo, hi);
                gv[g] = (odd ? hi : lo) + xg[g];
            }
            float cn = sigm(gv[1]) * c + sigm(gv[0]) * tanhf(gv[2]);
            float hn = sigm(gv[3]) * tanhf(cn);
            bool m = (tt < mylen);
            hout = m ? hn : h_s[rbuf][ucol * HROW + ks];
            if (m) c = cn;
        }
        if (active) {
            if (!last) {
                uint32_t off = (uint32_t)((wbuf * (H_ * HROW) + ucol * HROW + ks) * 4);
#pragma unroll
                for (int r = 0; r < 8; r++) st_cluster_f32(rbase[r] + off, hout);
            }
            g_h1[(size_t)(bglob * L_ + tt) * ENC_ + dir * H_ + ucol] = hout;
            if (!last) {
                int tn = dir ? (L_ - 2 - step) : (step + 1);
                const float* xp = g_xproj + (size_t)(bglob * L_ + tn) * XCOLS + dir * GATE_ + ucol;
#pragma unroll
                for (int g = 0; g < 4; g++) xg[g] = __ldg(&xp[g * H_]);
            }
        }
        if (!last) {
            __syncwarp();
            if (lane < 8)
                asm volatile("mbarrier.arrive.shared::cluster.b64 _, [%0];"
                             :: "r"(mbar_peer) : "memory");
            // wait for all 56 arrivals of this phase
            {
                uint32_t parity = (uint32_t)(step & 1);
                asm volatile(
                    "{\n\t"
                    ".reg .pred P;\n\t"
                    "WAIT_%=:\n\t"
                    "mbarrier.try_wait.parity.acquire.cluster.shared::cta.b64 P, [%0], %1, 0x989680;\n\t"
                    "@!P bra WAIT_%=;\n\t"
                    "}"
                    :: "r"(mbar), "r"(parity) : "memory");
            }
        }
        rbuf = wbuf;
    }
    asm volatile("barrier.cluster.arrive.aligned;" ::: "memory");
    asm volatile("barrier.cluster.wait.aligned;" ::: "memory");
}

// ---- GEMM2: KV = h1 @ [Wk|Wv], KTILE=16 pipelined ----
__global__ __launch_bounds__(256) void gemm_kv_kernel(
    const float* __restrict__ Wk, const float* __restrict__ Wv) {
    __shared__ float As[2][16][132];
    __shared__ float Bs[2][16][132];
    const int NT = 25;
    int bn = blockIdx.x * 128, bm = blockIdx.y * 128;
    int tid = threadIdx.x, tx = tid & 15, ty = tid >> 4;
    ull acc2[8][4];
#pragma unroll
    for (int i = 0; i < 8; i++)
#pragma unroll
        for (int j = 0; j < 4; j++) acc2[i][j] = 0ULL;
    int ar = tid >> 1, akb = (tid & 1) * 8;
    int bk = tid >> 5, bcb = (tid & 31) * 4;
    const float* arow = g_h1 + (size_t)(bm + ar) * ENC_;
    int bcol = bn + bcb;
    bool bcok = (bcol + 3) < 800;
    const float* bsrc = (bcol < ENC_) ? (Wk + bcol) : (Wv + (bcol - ENC_));

    float4 a0R, a1R, a0N, a1N;
    {
        a0R = *(const float4*)(arow + akb);
        a1R = *(const float4*)(arow + akb + 4);
        cpa16(smem_u32(&Bs[0][bk][bcb]),     bsrc + (size_t)bk * ENC_,       bcok);
        cpa16(smem_u32(&Bs[0][bk + 8][bcb]), bsrc + (size_t)(bk + 8) * ENC_, bcok);
        cpa_commit();
    }
    for (int it = 0; it < NT; ++it) {
        int buf = it & 1;
        As[buf][akb + 0][ar] = a0R.x; As[buf][akb + 1][ar] = a0R.y;
        As[buf][akb + 2][ar] = a0R.z; As[buf][akb + 3][ar] = a0R.w;
        As[buf][akb + 4][ar] = a1R.x; As[buf][akb + 5][ar] = a1R.y;
        As[buf][akb + 6][ar] = a1R.z; As[buf][akb + 7][ar] = a1R.w;
        if (it + 1 < NT) {
            int k0 = (it + 1) * 16;
            a0N = *(const float4*)(arow + k0 + akb);
            a1N = *(const float4*)(arow + k0 + akb + 4);
            cpa16(smem_u32(&Bs[buf ^ 1][bk][bcb]),     bsrc + (size_t)(k0 + bk) * ENC_,     bcok);
            cpa16(smem_u32(&Bs[buf ^ 1][bk + 8][bcb]), bsrc + (size_t)(k0 + bk + 8) * ENC_, bcok);
            cpa_commit();
            cpa_wait<1>();
        } else {
            cpa_wait<0>();
        }
        __syncthreads();
#pragma unroll
        for (int k = 0; k < 16; k++) {
            float4 a0 = *(const float4*)&As[buf][k][ty * 8];
            float4 a1 = *(const float4*)&As[buf][k][ty * 8 + 4];
            float4 b0 = *(const float4*)&Bs[buf][k][tx * 8];
            float4 b1 = *(const float4*)&Bs[buf][k][tx * 8 + 4];
            float a[8] = {a0.x, a0.y, a0.z, a0.w, a1.x, a1.y, a1.z, a1.w};
            ull bb2[4] = {pk2(b0.x, b0.y), pk2(b0.z, b0.w), pk2(b1.x, b1.y), pk2(b1.z, b1.w)};
#pragma unroll
            for (int i = 0; i < 8; i++) {
                ull ad = pk2(a[i], a[i]);
#pragma unroll
                for (int j = 0; j < 4; j++) acc2[i][j] = ffma2(ad, bb2[j], acc2[i][j]);
            }
        }
        __syncthreads();
        a0R = a0N; a1R = a1N;
    }
#pragma unroll
    for (int i = 0; i < 8; i++) {
        int r = bm + ty * 8 + i;
#pragma unroll
        for (int j = 0; j < 4; j++) {
            float v0, v1; upk2(acc2[i][j], v0, v1);
            int cix = bn + tx * 8 + 2 * j;
            if (cix < 800) g_KV[(size_t)r * 800 + cix] = v0;
            if (cix + 1 < 800) g_KV[(size_t)r * 800 + cix + 1] = v1;
        }
    }
}

__device__ __forceinline__ float bsum(float v, float* red) {
#pragma unroll
    for (int o = 16; o; o >>= 1) v += __shfl_xor_sync(0xffffffffu, v, o);
    int lane = threadIdx.x & 31, warp = threadIdx.x >> 5;
    __syncthreads();
    if (lane == 0) red[warp] = v;
    __syncthreads();
    float r = red[0];
#pragma unroll
    for (int i = 1; i < 8; i++) r += red[i];
    return r;
}
__device__ __forceinline__ float bmax(float v, float* red) {
#pragma unroll
    for (int o = 16; o; o >>= 1) v = fmaxf(v, __shfl_xor_sync(0xffffffffu, v, o));
    int lane = threadIdx.x & 31, warp = threadIdx.x >> 5;
    __syncthreads();
    if (lane == 0) red[warp] = v;
    __syncthreads();
    float r = red[0];
#pragma unroll
    for (int i = 1; i < 8; i++) r = fmaxf(r, red[i]);
    return r;
}

// ---- budget projection with fused score computation, block per (b,h) ----
__global__ __launch_bounds__(256) void budget_kernel(const float* __restrict__ q,
                                                     const unsigned char* __restrict__ mask) {
    __shared__ float red[8];
    __shared__ float qs[DH_];
    int b = blockIdx.x, h = blockIdx.y, l = threadIdx.x;
    if (l < DH_) qs[l] = q[h * DH_ + l];
    __syncthreads();

    const float4* kr = (const float4*)(g_KV + (size_t)(b * L_ + l) * 800 + h * DH_);
    const float4* q4 = (const float4*)qs;
    float a0 = 0.f, a1 = 0.f;
#pragma unroll
    for (int i = 0; i < 25; i += 2) {
        float4 v = kr[i], qv = q4[i];
        a0 += v.x * qv.x + v.y * qv.y + v.z * qv.z + v.w * qv.w;
        if (i + 1 < 25) {
            float4 v2 = kr[i + 1], qv2 = q4[i + 1];
            a1 += v2.x * qv2.x + v2.y * qv2.y + v2.z * qv2.z + v2.w * qv2.w;
        }
    }
    float s_raw = 1000.0f * (a0 + a1);

    bool m = mk(mask, b * L_ + l);
    float s = m ? s_raw : -1e9f;
    float budget = roundf(0.2f * (float)g_len[b]);
    float p0 = fminf(fmaxf(s, 0.f), 1.f);
    bool need = bsum(p0, red) > budget;
    float hi = bmax(m ? s : 0.f, red) + 1.f;
    float lo = 0.f;
    for (int it = 0; it < 60; it++) {
        float mid = 0.5f * (lo + hi);
        float val = bsum(fminf(fmaxf(s - mid, 0.f), 1.f), red);
        if (val > budget) lo = mid; else hi = mid;
    }
    float tau0 = 0.5f * (lo + hi);
    float r = s - tau0;
    bool fr = (r > 0.f) && (r < 1.f) && m;
    bool h1f = (r >= 1.f) && m;
    float nfree = bsum(fr ? 1.f : 0.f, red);
    float sfree = bsum(fr ? s : 0.f, red);
    float nhi = bsum(h1f ? 1.f : 0.f, red);
    float tau = (sfree + nhi - budget) / fmaxf(nfree, 1.f);
    tau = (nfree > 0.f) ? tau : tau0;
    float pv = fminf(fmaxf(s - tau, 0.f), 1.f);
    g_p[((b * NH_ + h) << 8) + l] = need ? pv : p0;
}

// ---- zp ----
__global__ void zp_kernel(const unsigned char* __restrict__ mask, float* __restrict__ out) {
    int b = blockIdx.x, l = threadIdx.x;
    float v = 0.f;
    if (mk(mask, b * L_ + l))
        v = 0.25f * (g_p[((b * NH_) << 8) + l] + g_p[((b * NH_ + 1) << 8) + l] +
                     g_p[((b * NH_ + 2) << 8) + l] + g_p[((b * NH_ + 3) << 8) + l]);
    out[B_ + b * L_ + l] = v;
}

// ---- pooled ----
__global__ __launch_bounds__(128) void pooled_kernel() {
    __shared__ float ps[L_];
    int b = blockIdx.x, h = blockIdx.y, d = threadIdx.x;
    for (int i = d; i < L_; i += 128) ps[i] = g_p[((b * NH_ + h) << 8) + i];
    __syncthreads();
    if (d >= DH_) return;
    const float* vb = g_KV + (size_t)(b * L_) * 800 + ENC_ + h * DH_ + d;
    float a0 = 0.f, a1 = 0.f, a2 = 0.f, a3 = 0.f;
#pragma unroll 4
    for (int l = 0; l < L_; l += 4) {
        a0 += ps[l] * vb[(size_t)l * 800];
        a1 += ps[l + 1] * vb[(size_t)(l + 1) * 800];
        a2 += ps[l + 2] * vb[(size_t)(l + 2) * 800];
        a3 += ps[l + 3] * vb[(size_t)(l + 3) * 800];
    }
    g_pooled[b * ENC_ + h * DH_ + d] = (a0 + a1) + (a2 + a3);
}

// ---- y ----
__global__ __launch_bounds__(128) void final_kernel(const float* __restrict__ outb,
                                                    float* __restrict__ out) {
    __shared__ float red[4];
    int b = blockIdx.x, tid = threadIdx.x;
    float v = 0.f;
    for (int i = tid; i < ENC_; i += 128) v += g_pooled[b * ENC_ + i] * g_weff[i];
#pragma unroll
    for (int o = 16; o; o >>= 1) v += __shfl_xor_sync(0xffffffffu, v, o);
    if ((tid & 31) == 0) red[tid >> 5] = v;
    __syncthreads();
    if (tid == 0) out[b] = sigm(red[0] + red[1] + red[2] + red[3] + outb[0]);
}

extern "C" void kernel_launch(void* const* d_in, const int* in_sizes, int n_in,
                              void* d_out, int out_size) {
    const int* x = (const int*)d_in[0];
    const unsigned char* mask = (const unsigned char*)d_in[2];
    const float* embW = (const float*)d_in[3];
    const float* Wif = (const float*)d_in[4];
    const float* Whf = (const float*)d_in[5];
    const float* bf = (const float*)d_in[6];
    const float* Wib = (const float*)d_in[7];
    const float* Whb = (const float*)d_in[8];
    const float* bb = (const float*)d_in[9];
    const float* Wk = (const float*)d_in[10];
    const float* Wv = (const float*)d_in[11];
    const float* q = (const float*)d_in[12];
    const float* Wo = (const float*)d_in[13];
    const float* outW = (const float*)d_in[14];
    const float* outb = (const float*)d_in[15];
    float* out = (float*)d_out;

    init_kernel<<<1, 512>>>(mask, Wo, outW);
    gemm_xproj_kernel<<<dim3(13, 128), 256>>>(x, embW, Wif, Wib, bf, bb);
    lstm_kernel<<<128, 224>>>(Whf, Whb);
    gemm_kv_kernel<<<dim3(7, 128), 256>>>(Wk, Wv);
    budget_kernel<<<dim3(B_, NH_), 256>>>(q, mask);
    zp_kernel<<<B_, L_>>>(mask, out);
    pooled_kernel<<<dim3(B_, NH_), 128>>>();
    final_kernel<<<B_, 128>>>(outb, out);
}